// round 13
// baseline (speedup 1.0000x reference)
#include <cuda_runtime.h>
#include <cuda_fp16.h>
#include <cstdint>
#include <cstddef>

// Problem constants
#define TT   1024
#define BB   512
#define II   32
#define HH   256
#define OO   32
#define KDIM 288
#define NCHUNK 18        // 288/16 k-chunks

#define NGRP 16          // batch groups (32 rows each) = clusters
#define CLUSTER 8        // CTAs per cluster, each owns 32 j
#define BT   32
#define NTHR 256         // 8 warps, warp w owns D rows [16w,16w+16)
#define MROWS 128        // gate rows per CTA, r = 4*j + gate
#define KP   296         // padded halfs per row
#define RB   592         // row bytes (rows mod 128 all distinct -> conflict-free ldsm)

typedef unsigned long long ull;

// Persistent scratch (no allocation allowed): out-proj partials only
__device__ __align__(16) float g_part[2][NGRP][CLUSTER][BT][OO];

// ---------- helpers ----------
__device__ __forceinline__ void ffma2(ull& acc, ull a, ull b) {
    asm("fma.rn.f32x2 %0, %1, %2, %0;" : "+l"(acc) : "l"(a), "l"(b));
}
__device__ __forceinline__ ull pack2(float a, float b) {
    ull r; asm("mov.b64 %0, {%1, %2};" : "=l"(r) : "f"(a), "f"(b)); return r;
}
__device__ __forceinline__ float2 unpack2(ull v) {
    float2 r; asm("mov.b64 {%0, %1}, %2;" : "=f"(r.x), "=f"(r.y) : "l"(v)); return r;
}
__device__ __forceinline__ float sigf(float x) {
    return __fdividef(1.0f, 1.0f + __expf(-x));
}
__device__ __forceinline__ float tanh_acc(float x) {
    float ax = fabsf(x);
    float e  = __expf(-2.0f * ax);
    float r  = __fdividef(1.0f - e, 1.0f + e);
    return copysignf(r, x);
}
__device__ __forceinline__ uint32_t h2u(__half2 h) { return *reinterpret_cast<uint32_t*>(&h); }

__device__ __forceinline__ uint32_t mapa_sh(uint32_t addr, uint32_t rank) {
    uint32_t d;
    asm("mapa.shared::cluster.u32 %0, %1, %2;" : "=r"(d) : "r"(addr), "r"(rank));
    return d;
}
__device__ __forceinline__ void st_cluster_u64(uint32_t addr, ull v) {
    asm volatile("st.shared::cluster.u64 [%0], %1;" :: "r"(addr), "l"(v) : "memory");
}
#define CLUSTER_SYNC() do { \
    asm volatile("barrier.cluster.arrive.aligned;" ::: "memory"); \
    asm volatile("barrier.cluster.wait.aligned;" ::: "memory"); \
} while (0)

__device__ __forceinline__ void ldsm4(uint32_t* r, uint32_t addr) {
    asm volatile("ldmatrix.sync.aligned.m8n8.x4.shared.b16 {%0,%1,%2,%3}, [%4];"
                 : "=r"(r[0]), "=r"(r[1]), "=r"(r[2]), "=r"(r[3]) : "r"(addr));
}
__device__ __forceinline__ void mma16816(float* d, const uint32_t* a, uint32_t b0, uint32_t b1) {
    asm volatile("mma.sync.aligned.m16n8k16.row.col.f32.f16.f16.f32 "
                 "{%0,%1,%2,%3}, {%4,%5,%6,%7}, {%8,%9}, {%0,%1,%2,%3};"
                 : "+f"(d[0]), "+f"(d[1]), "+f"(d[2]), "+f"(d[3])
                 : "r"(a[0]), "r"(a[1]), "r"(a[2]), "r"(a[3]), "r"(b0), "r"(b1));
}

// smem byte offsets
#define OFF_A_HI   0          // half[128][296] = 75776
#define OFF_A_LO   75776      // -> 151552
#define OFF_B0     151552     // half[32][296] = 18944 (stage 0)
#define OFF_B1     170496     // stage 1 -> 189440
#define OFF_GATES  189440     // float[128][36] = 18432 -> 207872
#define OFF_HT     207872     // float[32][34]  = 4352 -> 212224
#define OFF_WOUT2  212224     // ull[32 o][17]  = 4352 -> 216576
#define OFF_BOUT   216576     // float[4]
#define SMEM_BYTES 216592

__global__ void __launch_bounds__(NTHR, 1) __cluster_dims__(CLUSTER, 1, 1)
lstm_kernel(const float* __restrict__ x, const float* __restrict__ phys,
            const float* __restrict__ Wih, const float* __restrict__ Whh,
            const float* __restrict__ bih, const float* __restrict__ bhh,
            const float* __restrict__ Wout, const float* __restrict__ bout,
            float* __restrict__ out) {
    extern __shared__ __align__(128) char smem[];
    uint32_t sbase;
    asm("{ .reg .u64 t; cvta.to.shared.u64 t, %1; cvt.u32.u64 %0, t; }" : "=r"(sbase) : "l"(smem));

    float* gates   = (float*)(smem + OFF_GATES);
    float* htile   = (float*)(smem + OFF_HT);
    ull*   wout2_s = (ull*)(smem + OFF_WOUT2);
    float* bout_s  = (float*)(smem + OFF_BOUT);

    const int tid  = threadIdx.x;
    const int cta  = blockIdx.x;
    const int grp  = cta >> 3;        // cluster id = batch group
    const int g8   = cta & 7;         // cluster rank = j-slice
    const int b0   = grp * BT;
    const int j0   = g8 * 32;
    const int w    = tid >> 5;
    const int lane = tid & 31;
    const int b    = tid >> 3;        // batch row 0..31 (staging/writeback map)
    const int s    = tid & 7;         // slice 0..7

    // ---- zero both B stages (pad cols 288..295 stay 0 forever) ----
    for (int i = tid; i < (2 * 18944) / 16; i += NTHR)
        ((uint4*)(smem + OFF_B0))[i] = make_uint4(0, 0, 0, 0);

    // ---- A = weights fp16 hi/lo, row r = 4j+gate, 592B stride ----
    for (int i = tid; i < MROWS * KP; i += NTHR) {
        int r = i / KP, k = i - r * KP;
        int j = r >> 2, g = r & 3;
        int grow = g * HH + j0 + j;
        float v = 0.0f;
        if (k < HH)        v = Whh[grow * HH + k];
        else if (k < KDIM) v = Wih[grow * II + (k - HH)];
        __half h = __float2half_rn(v);
        __half l = __float2half_rn(v - __half2float(h));
        *(__half*)(smem + OFF_A_HI + r * RB + k * 2) = h;
        *(__half*)(smem + OFF_A_LO + r * RB + k * 2) = l;
    }
    // Wout pairs over OWN j-slice, all 32 o
    for (int i = tid; i < 32 * 16; i += NTHR) {
        int o = i >> 4, jp = i & 15;
        wout2_s[o * 17 + jp] = pack2(Wout[o * HH + j0 + 2 * jp],
                                     Wout[o * HH + j0 + 2 * jp + 1]);
    }
    if (tid < 4) bout_s[tid] = bout[g8 * 4 + tid];

    // MMA fragment lane mapping (validated R8-R10)
    const int m  = lane >> 3;
    const int r8 = lane & 7;
    const int gq = lane >> 2;
    const int tg = lane & 3;
    const uint32_t aHi = sbase + OFF_A_HI + (16 * w + ((m & 1) << 3) + r8) * RB + ((m >> 1) << 4);
    const uint32_t aLo = aHi + (OFF_A_LO - OFF_A_HI);
    const uint32_t bOff = (((m >> 1) << 3) + r8) * RB + ((m & 1) << 4);

    // bias folded into D-register init (rows 16w+gq, 16w+gq+8)
    float bias_lo, bias_hi;
    {
        int r1 = 16 * w + gq, r2 = r1 + 8;
        int j1 = r1 >> 2, gg1 = r1 & 3, j2 = r2 >> 2, gg2 = r2 & 3;
        bias_lo = bih[gg1 * HH + j0 + j1] + bhh[gg1 * HH + j0 + j1];
        bias_hi = bih[gg2 * HH + j0 + j2] + bhh[gg2 * HH + j0 + j2];
    }

    float c[4] = {0.f, 0.f, 0.f, 0.f};    // cell state: (j=tid>>3, batches 4s..4s+4)
    __syncthreads();

    // ---- stage x(0) into B0 (h(0)=0 already via zero fill) ----
    {
        float4 xv = *(const float4*)(x + ((size_t)0 * BB + b0 + b) * II + 4 * s);
        uint32_t u0 = h2u(__floats2half2_rn(xv.x, xv.y));
        uint32_t u1 = h2u(__floats2half2_rn(xv.z, xv.w));
        *(uint2*)(smem + OFF_B0 + b * RB + 512 + s * 8) = make_uint2(u0, u1);
    }
    // all CTAs' tiles initialized before any peer pushes into them
    CLUSTER_SYNC();

    for (int t = 0; t < TT; ++t) {
        const uint32_t offBc = (t & 1) ? OFF_B1 : OFF_B0;       // current stage
        const uint32_t offBn = (t & 1) ? OFF_B0 : OFF_B1;       // next stage

        // ---- prefetches (global, independent of cluster state) ----
        float4 xv = make_float4(0.f, 0.f, 0.f, 0.f);
        if (t + 1 < TT)
            xv = *(const float4*)(x + ((size_t)(t + 1) * BB + b0 + b) * II + 4 * s);
        float phv = 0.0f;
        if (t > 0 && tid < 128)
            phv = phys[((size_t)(t - 1) * BB + b0 + (tid >> 2)) * OO + g8 * 4 + (tid & 3)];

        // ---- gate GEMM: 2-pass (Whi + Wlo) x h_fp16, B in local smem already ----
        float d[4][4];
#pragma unroll
        for (int nt = 0; nt < 4; ++nt) {
            d[nt][0] = bias_lo; d[nt][1] = bias_lo;
            d[nt][2] = bias_hi; d[nt][3] = bias_hi;
        }
        const uint32_t bAd = sbase + offBc + bOff;
#pragma unroll 6
        for (int kc = 0; kc < NCHUNK; ++kc) {
            uint32_t a[4], a2[4], qh[8];
            ldsm4(a,      aHi + kc * 32);
            ldsm4(qh,     bAd + kc * 32);
            ldsm4(qh + 4, bAd + 16 * RB + kc * 32);
            ldsm4(a2,     aLo + kc * 32);
            mma16816(d[0], a,  qh[0], qh[1]);
            mma16816(d[1], a,  qh[2], qh[3]);
            mma16816(d[2], a,  qh[4], qh[5]);
            mma16816(d[3], a,  qh[6], qh[7]);
            mma16816(d[0], a2, qh[0], qh[1]);
            mma16816(d[1], a2, qh[2], qh[3]);
            mma16816(d[2], a2, qh[4], qh[5]);
            mma16816(d[3], a2, qh[6], qh[7]);
        }
        // D -> gates[row][batch] (stride 36)
        {
            float* glo = gates + (16 * w + gq) * 36 + 2 * tg;
            float* ghi = glo + 8 * 36;
#pragma unroll
            for (int nt = 0; nt < 4; ++nt) {
                glo[8 * nt] = d[nt][0]; glo[8 * nt + 1] = d[nt][1];
                ghi[8 * nt] = d[nt][2]; ghi[8 * nt + 1] = d[nt][3];
            }
        }

        // ---- output for step t-1 (partials ordered by last cluster.sync) ----
        if (t > 0 && tid < 128) {
            int bq = tid >> 2, o = tid & 3, oc = g8 * 4 + o;
            float rnn = bout_s[o];
            const float* pp = &g_part[t & 1][grp][0][bq][oc];
#pragma unroll
            for (int p = 0; p < CLUSTER; ++p) rnn += pp[(size_t)p * BT * OO];
            size_t oi = ((size_t)(b0 + bq) * TT + (t - 1)) * OO + oc;
            out[oi] = phv + rnn;
            out[(size_t)BB * TT * OO + oi] = rnn;
        }
        __syncthreads();

        // ---- LSTM epilogue: thread = (j = tid>>3, batches 4s..4s+4) ----
        {
            int j = tid >> 3;
            const float* gr = gates + (4 * j) * 36 + 4 * s;
            float4 vi = *(const float4*)(gr);
            float4 vf = *(const float4*)(gr + 36);
            float4 vg = *(const float4*)(gr + 72);
            float4 vo = *(const float4*)(gr + 108);
            float gi_[4] = {vi.x, vi.y, vi.z, vi.w};
            float gf_[4] = {vf.x, vf.y, vf.z, vf.w};
            float gg_[4] = {vg.x, vg.y, vg.z, vg.w};
            float go_[4] = {vo.x, vo.y, vo.z, vo.w};
#pragma unroll
            for (int i = 0; i < 4; ++i) {
                float ig = sigf(gi_[i]), fg = sigf(gf_[i]);
                float gt = tanh_acc(gg_[i]), og = sigf(go_[i]);
                float cn = fg * c[i] + ig * gt;
                c[i] = cn;
                htile[(4 * s + i) * 34 + j] = og * tanh_acc(cn);
            }
        }
        __syncthreads();

        // ---- tail: push h(t+1) to all peers' next-stage B via DSMEM ----
        if (t + 1 < TT) {
            float f0 = htile[b * 34 + 4 * s + 0];
            float f1 = htile[b * 34 + 4 * s + 1];
            float f2 = htile[b * 34 + 4 * s + 2];
            float f3 = htile[b * 34 + 4 * s + 3];
            uint32_t u0 = h2u(__floats2half2_rn(f0, f1));
            uint32_t u1 = h2u(__floats2half2_rn(f2, f3));
            ull hv = ((ull)u1 << 32) | (ull)u0;
            uint32_t dst = sbase + offBn + b * RB + j0 * 2 + 8 * s;
#pragma unroll
            for (int p = 0; p < CLUSTER; ++p)
                st_cluster_u64(mapa_sh(dst, p), hv);
            // stage x(t+1) locally into next-stage B cols 256..287
            uint32_t xu0 = h2u(__floats2half2_rn(xv.x, xv.y));
            uint32_t xu1 = h2u(__floats2half2_rn(xv.z, xv.w));
            *(uint2*)(smem + offBn + b * RB + 512 + s * 8) = make_uint2(xu0, xu1);
        }
        // ---- out-proj partial from htile -> global (read at t+1) ----
        {
            int o4 = 4 * s;
            const ull* hrow2 = (const ull*)(htile + b * 34);
            ull pa0 = 0ull, pa1 = 0ull, pa2 = 0ull, pa3 = 0ull;
#pragma unroll
            for (int jp = 0; jp < 16; ++jp) {
                ull h2 = hrow2[jp];
                ffma2(pa0, h2, wout2_s[(o4 + 0) * 17 + jp]);
                ffma2(pa1, h2, wout2_s[(o4 + 1) * 17 + jp]);
                ffma2(pa2, h2, wout2_s[(o4 + 2) * 17 + jp]);
                ffma2(pa3, h2, wout2_s[(o4 + 3) * 17 + jp]);
            }
            float2 q0 = unpack2(pa0), q1 = unpack2(pa1);
            float2 q2 = unpack2(pa2), q3 = unpack2(pa3);
            *(float4*)(&g_part[(t + 1) & 1][grp][g8][b][o4]) =
                make_float4(q0.x + q0.y, q1.x + q1.y, q2.x + q2.y, q3.x + q3.y);
        }

        // ---- one cluster barrier per step: orders DSMEM pushes + g_part ----
        CLUSTER_SYNC();
    }

    // ---- final output for step TT-1 ----
    if (tid < 128) {
        int bq = tid >> 2, o = tid & 3, oc = g8 * 4 + o;
        float phv = phys[((size_t)(TT - 1) * BB + b0 + bq) * OO + oc];
        float rnn = bout_s[o];
        const float* pp = &g_part[TT & 1][grp][0][bq][oc];
#pragma unroll
        for (int p = 0; p < CLUSTER; ++p) rnn += pp[(size_t)p * BT * OO];
        size_t oi = ((size_t)(b0 + bq) * TT + (TT - 1)) * OO + oc;
        out[oi] = phv + rnn;
        out[(size_t)BB * TT * OO + oi] = rnn;
    }
}

extern "C" void kernel_launch(void* const* d_in, const int* in_sizes, int n_in,
                              void* d_out, int out_size) {
    const float* x    = (const float*)d_in[0];
    const float* phys = (const float*)d_in[1];
    const float* Wih  = (const float*)d_in[2];
    const float* Whh  = (const float*)d_in[3];
    const float* bih  = (const float*)d_in[4];
    const float* bhh  = (const float*)d_in[5];
    const float* Wout = (const float*)d_in[6];
    const float* bout = (const float*)d_in[7];
    float* out = (float*)d_out;

    cudaFuncSetAttribute(lstm_kernel,
                         cudaFuncAttributeMaxDynamicSharedMemorySize,
                         SMEM_BYTES);

    lstm_kernel<<<NGRP * CLUSTER, NTHR, SMEM_BYTES>>>(x, phys, Wih, Whh, bih, bhh,
                                                      Wout, bout, out);
}

// round 14
// speedup vs baseline: 1.7410x; 1.7410x over previous
#include <cuda_runtime.h>
#include <cuda_fp16.h>
#include <cstdint>
#include <cstddef>

// Problem constants
#define TT   1024
#define BB   512
#define II   32
#define HH   256
#define OO   32
#define KDIM 288
#define NCHUNK 18        // 288/16 k-chunks

#define NGRP 16          // batch groups (32 rows each)
#define BT   32
#define NTHR 256         // 8 warps, warp w owns D rows [16w,16w+16)
#define MROWS 128        // gate rows per CTA, r = 4*j + gate
#define KP   296         // padded halfs per row
#define RB   592         // row bytes (rows mod 128 all distinct -> conflict-free ldsm)

typedef unsigned long long ull;

// Persistent scratch (no allocation allowed)
__device__ __align__(16) __half g_hf16[2][NGRP][BT][HH];    // h fp16 [par][grp][b][j]
__device__ __align__(16) float  g_part[2][NGRP][8][BT][OO]; // out-proj partials
__device__ unsigned             g_bar[NGRP];

__global__ void init_kernel() {
    int idx = blockIdx.x * blockDim.x + threadIdx.x;
    if (idx < 131072) ((unsigned*)g_hf16)[idx] = 0u;        // zero both parities
    if (idx < NGRP) g_bar[idx] = 0u;
}

// ---------- helpers ----------
__device__ __forceinline__ void ffma2(ull& acc, ull a, ull b) {
    asm("fma.rn.f32x2 %0, %1, %2, %0;" : "+l"(acc) : "l"(a), "l"(b));
}
__device__ __forceinline__ ull pack2(float a, float b) {
    ull r; asm("mov.b64 %0, {%1, %2};" : "=l"(r) : "f"(a), "f"(b)); return r;
}
__device__ __forceinline__ float2 unpack2(ull v) {
    float2 r; asm("mov.b64 {%0, %1}, %2;" : "=f"(r.x), "=f"(r.y) : "l"(v)); return r;
}
__device__ __forceinline__ unsigned ld_acquire_u32(const unsigned* p) {
    unsigned v;
    asm volatile("ld.acquire.gpu.u32 %0, [%1];" : "=r"(v) : "l"(p));
    return v;
}
__device__ __forceinline__ void red_release_add(unsigned* p, unsigned v) {
    asm volatile("red.release.gpu.global.add.u32 [%0], %1;" :: "l"(p), "r"(v) : "memory");
}
__device__ __forceinline__ float sigf(float x) {
    return __fdividef(1.0f, 1.0f + __expf(-x));
}
__device__ __forceinline__ float tanh_acc(float x) {
    float ax = fabsf(x);
    float e  = __expf(-2.0f * ax);
    float r  = __fdividef(1.0f - e, 1.0f + e);
    return copysignf(r, x);
}
__device__ __forceinline__ uint32_t h2u(__half2 h) { return *reinterpret_cast<uint32_t*>(&h); }

__device__ __forceinline__ void ldsm4(uint32_t* r, uint32_t addr) {
    asm volatile("ldmatrix.sync.aligned.m8n8.x4.shared.b16 {%0,%1,%2,%3}, [%4];"
                 : "=r"(r[0]), "=r"(r[1]), "=r"(r[2]), "=r"(r[3]) : "r"(addr));
}
__device__ __forceinline__ void mma16816(float* d, const uint32_t* a, uint32_t b0, uint32_t b1) {
    asm volatile("mma.sync.aligned.m16n8k16.row.col.f32.f16.f16.f32 "
                 "{%0,%1,%2,%3}, {%4,%5,%6,%7}, {%8,%9}, {%0,%1,%2,%3};"
                 : "+f"(d[0]), "+f"(d[1]), "+f"(d[2]), "+f"(d[3])
                 : "r"(a[0]), "r"(a[1]), "r"(a[2]), "r"(a[3]), "r"(b0), "r"(b1));
}

// smem byte offsets
#define OFF_A_HI   0          // half[128][296] = 75776
#define OFF_A_LO   75776      // -> 151552
#define OFF_B_HI   151552     // half[32][296] = 18944 -> 170496
#define OFF_GATES  170496     // float[128][36] = 18432 -> 188928
#define OFF_HT     188928     // float[32][34]  = 4352 -> 193280
#define OFF_WOUT2  193280     // ull[32 o][17]  = 4352 -> 197632
#define OFF_BOUT   197632     // float[4]
#define SMEM_BYTES 197648

__global__ void __launch_bounds__(NTHR, 1)
lstm_kernel(const float* __restrict__ x, const float* __restrict__ phys,
            const float* __restrict__ Wih, const float* __restrict__ Whh,
            const float* __restrict__ bih, const float* __restrict__ bhh,
            const float* __restrict__ Wout, const float* __restrict__ bout,
            float* __restrict__ out) {
    extern __shared__ __align__(128) char smem[];
    uint32_t sbase;
    asm("{ .reg .u64 t; cvta.to.shared.u64 t, %1; cvt.u32.u64 %0, t; }" : "=r"(sbase) : "l"(smem));

    float* gates   = (float*)(smem + OFF_GATES);
    float* htile   = (float*)(smem + OFF_HT);
    ull*   wout2_s = (ull*)(smem + OFF_WOUT2);
    float* bout_s  = (float*)(smem + OFF_BOUT);

    const int tid  = threadIdx.x;
    const int cta  = blockIdx.x;
    const int grp  = cta >> 3;
    const int g8   = cta & 7;
    const int b0   = grp * BT;
    const int j0   = g8 * 32;
    const int w    = tid >> 5;
    const int lane = tid & 31;
    const int b    = tid >> 3;     // batch row 0..31 (staging/epilogue map)
    const int s    = tid & 7;      // k-slice 0..7

    // ---- zero B tile once (pad cols 288..295 stay 0 forever) ----
    for (int i = tid; i < 18944 / 16; i += NTHR)
        ((uint4*)(smem + OFF_B_HI))[i] = make_uint4(0, 0, 0, 0);

    // ---- A = weights fp16 hi/lo, row r = 4j+gate, 592B stride ----
    for (int i = tid; i < MROWS * KP; i += NTHR) {
        int r = i / KP, k = i - r * KP;
        int j = r >> 2, g = r & 3;
        int grow = g * HH + j0 + j;
        float v = 0.0f;
        if (k < HH)        v = Whh[grow * HH + k];
        else if (k < KDIM) v = Wih[grow * II + (k - HH)];
        __half h = __float2half_rn(v);
        __half l = __float2half_rn(v - __half2float(h));
        *(__half*)(smem + OFF_A_HI + r * RB + k * 2) = h;
        *(__half*)(smem + OFF_A_LO + r * RB + k * 2) = l;
    }
    // Wout pairs over OWN j-slice, all 32 o
    for (int i = tid; i < 32 * 16; i += NTHR) {
        int o = i >> 4, jp = i & 15;
        wout2_s[o * 17 + jp] = pack2(Wout[o * HH + j0 + 2 * jp],
                                     Wout[o * HH + j0 + 2 * jp + 1]);
    }
    if (tid < 4) bout_s[tid] = bout[g8 * 4 + tid];

    // MMA fragment lane mapping (validated R8-R10)
    const int m  = lane >> 3;
    const int r8 = lane & 7;
    const int gq = lane >> 2;
    const int tg = lane & 3;
    const uint32_t aHi = sbase + OFF_A_HI + (16 * w + ((m & 1) << 3) + r8) * RB + ((m >> 1) << 4);
    const uint32_t aLo = aHi + (OFF_A_LO - OFF_A_HI);
    const uint32_t bHi = sbase + OFF_B_HI + (((m >> 1) << 3) + r8) * RB + ((m & 1) << 4);

    // bias folded into D-register init (rows 16w+gq, 16w+gq+8)
    float bias_lo, bias_hi;
    {
        int r1 = 16 * w + gq, r2 = r1 + 8;
        int j1 = r1 >> 2, gg1 = r1 & 3, j2 = r2 >> 2, gg2 = r2 & 3;
        bias_lo = bih[gg1 * HH + j0 + j1] + bhh[gg1 * HH + j0 + j1];
        bias_hi = bih[gg2 * HH + j0 + j2] + bhh[gg2 * HH + j0 + j2];
    }

    float c[4] = {0.f, 0.f, 0.f, 0.f};    // cell state: (j=tid>>3, batches 4s..4s+4)
    __syncthreads();

    for (int t = 0; t <= TT; ++t) {
        // ---- peer-independent prefetch + convert BEFORE the spin ----
        uint32_t xh0u = 0, xh1u = 0;
        if (t < TT) {
            float4 xv = *(const float4*)(x + ((size_t)t * BB + b0 + b) * II + s * 4);
            xh0u = h2u(__floats2half2_rn(xv.x, xv.y));
            xh1u = h2u(__floats2half2_rn(xv.z, xv.w));
        }
        float phv = 0.0f;
        if (t > 0 && tid < 128)
            phv = phys[((size_t)(t - 1) * BB + b0 + (tid >> 2)) * OO + g8 * 4 + (tid & 3)];

        // ---- group barrier: per-warp acquire spin (64 arrivals per step) ----
        if (t > 0) {
            if (lane == 0) {
                unsigned target = 64u * (unsigned)t;
                while (ld_acquire_u32(&g_bar[grp]) < target) { }
            }
            __syncwarp();
        }

        if (t < TT) {
            // ---- stage h(t): pure fp16 copy (producer already converted) ----
            const uint4* hi4 = (const uint4*)&g_hf16[t & 1][grp][b][s * 32];
            char* dhi = smem + OFF_B_HI + b * RB + s * 64;
#pragma unroll
            for (int mm = 0; mm < 4; ++mm)
                *(uint4*)(dhi + mm * 16) = hi4[mm];
            // stage x(t) (pre-converted) into B cols 256..287
            *(uint2*)(smem + OFF_B_HI + b * RB + 512 + s * 8) = make_uint2(xh0u, xh1u);
        }

        if (t == TT) {
            // final output for step TT-1 (no smem dependency)
            if (tid < 128) {
                int bq = tid >> 2, o = tid & 3, oc = g8 * 4 + o;
                float rnn = bout_s[o];
                const float* pp = &g_part[t & 1][grp][0][bq][oc];
#pragma unroll
                for (int p = 0; p < 8; ++p) rnn += pp[(size_t)p * BT * OO];
                size_t oi = ((size_t)(b0 + bq) * TT + (t - 1)) * OO + oc;
                out[oi] = phv + rnn;
                out[(size_t)BB * TT * OO + oi] = rnn;
            }
            break;
        }
        __syncthreads();

        // ---- gate GEMM: 2-pass fp16-split (Whi + Wlo) x h_fp16 ----
        float d[4][4];
#pragma unroll
        for (int nt = 0; nt < 4; ++nt) {
            d[nt][0] = bias_lo; d[nt][1] = bias_lo;
            d[nt][2] = bias_hi; d[nt][3] = bias_hi;
        }
#pragma unroll 6
        for (int kc = 0; kc < NCHUNK; ++kc) {
            uint32_t a[4], a2[4], qh[8];
            ldsm4(a,      aHi + kc * 32);
            ldsm4(qh,     bHi + kc * 32);
            ldsm4(qh + 4, bHi + 16 * RB + kc * 32);
            ldsm4(a2,     aLo + kc * 32);
            mma16816(d[0], a,  qh[0], qh[1]);
            mma16816(d[1], a,  qh[2], qh[3]);
            mma16816(d[2], a,  qh[4], qh[5]);
            mma16816(d[3], a,  qh[6], qh[7]);
            mma16816(d[0], a2, qh[0], qh[1]);
            mma16816(d[1], a2, qh[2], qh[3]);
            mma16816(d[2], a2, qh[4], qh[5]);
            mma16816(d[3], a2, qh[6], qh[7]);
        }
        // D -> gates[row][batch] (stride 36)
        {
            float* glo = gates + (16 * w + gq) * 36 + 2 * tg;
            float* ghi = glo + 8 * 36;
#pragma unroll
            for (int nt = 0; nt < 4; ++nt) {
                glo[8 * nt] = d[nt][0]; glo[8 * nt + 1] = d[nt][1];
                ghi[8 * nt] = d[nt][2]; ghi[8 * nt + 1] = d[nt][3];
            }
        }

        // ---- output for step t-1 (overlaps the gates sync) ----
        if (t > 0 && tid < 128) {
            int bq = tid >> 2, o = tid & 3, oc = g8 * 4 + o;
            float rnn = bout_s[o];
            const float* pp = &g_part[t & 1][grp][0][bq][oc];
#pragma unroll
            for (int p = 0; p < 8; ++p) rnn += pp[(size_t)p * BT * OO];
            size_t oi = ((size_t)(b0 + bq) * TT + (t - 1)) * OO + oc;
            out[oi] = phv + rnn;
            out[(size_t)BB * TT * OO + oi] = rnn;
        }
        __syncthreads();

        // ---- LSTM epilogue: thread = (j = tid>>3, batches 4s..4s+4) ----
        {
            int j = tid >> 3;
            const float* gr = gates + (4 * j) * 36 + 4 * s;
            float4 vi = *(const float4*)(gr);
            float4 vf = *(const float4*)(gr + 36);
            float4 vg = *(const float4*)(gr + 72);
            float4 vo = *(const float4*)(gr + 108);
            float gi_[4] = {vi.x, vi.y, vi.z, vi.w};
            float gf_[4] = {vf.x, vf.y, vf.z, vf.w};
            float gg_[4] = {vg.x, vg.y, vg.z, vg.w};
            float go_[4] = {vo.x, vo.y, vo.z, vo.w};
#pragma unroll
            for (int i = 0; i < 4; ++i) {
                float ig = sigf(gi_[i]), fg = sigf(gf_[i]);
                float gt = tanh_acc(gg_[i]), og = sigf(go_[i]);
                float cn = fg * c[i] + ig * gt;
                c[i] = cn;
                htile[(4 * s + i) * 34 + j] = og * tanh_acc(cn);
            }
        }
        __syncthreads();

        // ---- writeback h as fp16 (producer-side cvt) + out-proj partial ----
        {
            float f0 = htile[b * 34 + 4 * s + 0];
            float f1 = htile[b * 34 + 4 * s + 1];
            float f2 = htile[b * 34 + 4 * s + 2];
            float f3 = htile[b * 34 + 4 * s + 3];
            __half2 h01 = __floats2half2_rn(f0, f1);
            __half2 h23 = __floats2half2_rn(f2, f3);
            *(uint2*)(&g_hf16[(t + 1) & 1][grp][b][j0 + 4 * s]) = make_uint2(h2u(h01), h2u(h23));
        }
        {
            int o4 = s * 4;
            const ull* hrow2 = (const ull*)(htile + b * 34);
            ull pa0 = 0ull, pa1 = 0ull, pa2 = 0ull, pa3 = 0ull;
#pragma unroll
            for (int jp = 0; jp < 16; ++jp) {
                ull h2 = hrow2[jp];
                ffma2(pa0, h2, wout2_s[(o4 + 0) * 17 + jp]);
                ffma2(pa1, h2, wout2_s[(o4 + 1) * 17 + jp]);
                ffma2(pa2, h2, wout2_s[(o4 + 2) * 17 + jp]);
                ffma2(pa3, h2, wout2_s[(o4 + 3) * 17 + jp]);
            }
            float2 q0 = unpack2(pa0), q1 = unpack2(pa1);
            float2 q2 = unpack2(pa2), q3 = unpack2(pa3);
            *(float4*)(&g_part[(t + 1) & 1][grp][g8][b][o4]) =
                make_float4(q0.x + q0.y, q1.x + q1.y, q2.x + q2.y, q3.x + q3.y);
        }
        // per-warp release: own STGs are ordered by red.release after syncwarp
        __syncwarp();
        if (lane == 0) red_release_add(&g_bar[grp], 1u);
    }
}

extern "C" void kernel_launch(void* const* d_in, const int* in_sizes, int n_in,
                              void* d_out, int out_size) {
    const float* x    = (const float*)d_in[0];
    const float* phys = (const float*)d_in[1];
    const float* Wih  = (const float*)d_in[2];
    const float* Whh  = (const float*)d_in[3];
    const float* bih  = (const float*)d_in[4];
    const float* bhh  = (const float*)d_in[5];
    const float* Wout = (const float*)d_in[6];
    const float* bout = (const float*)d_in[7];
    float* out = (float*)d_out;

    cudaFuncSetAttribute(lstm_kernel,
                         cudaFuncAttributeMaxDynamicSharedMemorySize,
                         SMEM_BYTES);

    init_kernel<<<(131072 + 255) / 256, 256>>>();
    lstm_kernel<<<NGRP * 8, NTHR, SMEM_BYTES>>>(x, phys, Wih, Whh, bih, bhh,
                                                Wout, bout, out);
}

// round 15
// speedup vs baseline: 1.9239x; 1.1051x over previous
#include <cuda_runtime.h>
#include <cuda_fp16.h>
#include <cstdint>
#include <cstddef>

// Problem constants
#define TT   1024
#define BB   512
#define II   32
#define HH   256
#define OO   32
#define KDIM 288
#define NCHUNK 18        // 288/16 k-chunks

#define NGRP 16          // batch groups (32 rows each)
#define BT   32
#define NTHR 256         // 8 warps, warp w owns D rows [16w,16w+16) = j [4w,4w+4)
#define MROWS 128        // gate rows per CTA, r = 4*j + gate
#define KP   296         // padded halfs per row
#define RB   592         // row bytes (rows mod 128 all distinct -> conflict-free ldsm)

typedef unsigned long long ull;

// Persistent scratch (no allocation allowed)
__device__ __align__(16) __half g_hf16[2][NGRP][BT][HH];    // h fp16 [par][grp][b][j]
__device__ __align__(16) float  g_part[2][NGRP][8][BT][OO]; // out-proj partials
__device__ unsigned             g_bar[NGRP][8][8];          // per-producer flags, 32B padded

__global__ void init_kernel() {
    int idx = blockIdx.x * blockDim.x + threadIdx.x;
    if (idx < 131072) ((unsigned*)g_hf16)[idx] = 0u;        // zero both parities
    if (idx < NGRP * 8 * 8) ((unsigned*)g_bar)[idx] = 0u;
}

// ---------- helpers ----------
__device__ __forceinline__ void ffma2(ull& acc, ull a, ull b) {
    asm("fma.rn.f32x2 %0, %1, %2, %0;" : "+l"(acc) : "l"(a), "l"(b));
}
__device__ __forceinline__ ull pack2(float a, float b) {
    ull r; asm("mov.b64 %0, {%1, %2};" : "=l"(r) : "f"(a), "f"(b)); return r;
}
__device__ __forceinline__ float2 unpack2(ull v) {
    float2 r; asm("mov.b64 {%0, %1}, %2;" : "=f"(r.x), "=f"(r.y) : "l"(v)); return r;
}
__device__ __forceinline__ unsigned ld_acquire_u32(const unsigned* p) {
    unsigned v;
    asm volatile("ld.acquire.gpu.u32 %0, [%1];" : "=r"(v) : "l"(p));
    return v;
}
__device__ __forceinline__ void red_release_add(unsigned* p, unsigned v) {
    asm volatile("red.release.gpu.global.add.u32 [%0], %1;" :: "l"(p), "r"(v) : "memory");
}
__device__ __forceinline__ float sigf(float x) {
    return __fdividef(1.0f, 1.0f + __expf(-x));
}
__device__ __forceinline__ float tanhfast(float x) {
    float y; asm("tanh.approx.f32 %0, %1;" : "=f"(y) : "f"(x)); return y;
}
__device__ __forceinline__ uint32_t h2u(__half2 h) { return *reinterpret_cast<uint32_t*>(&h); }

__device__ __forceinline__ void ldsm4(uint32_t* r, uint32_t addr) {
    asm volatile("ldmatrix.sync.aligned.m8n8.x4.shared.b16 {%0,%1,%2,%3}, [%4];"
                 : "=r"(r[0]), "=r"(r[1]), "=r"(r[2]), "=r"(r[3]) : "r"(addr));
}
__device__ __forceinline__ void mma16816(float* d, const uint32_t* a, uint32_t b0, uint32_t b1) {
    asm volatile("mma.sync.aligned.m16n8k16.row.col.f32.f16.f16.f32 "
                 "{%0,%1,%2,%3}, {%4,%5,%6,%7}, {%8,%9}, {%0,%1,%2,%3};"
                 : "+f"(d[0]), "+f"(d[1]), "+f"(d[2]), "+f"(d[3])
                 : "r"(a[0]), "r"(a[1]), "r"(a[2]), "r"(a[3]), "r"(b0), "r"(b1));
}

// smem byte offsets
#define OFF_A_HI   0          // half[128][296] = 75776
#define OFF_A_LO   75776      // -> 151552
#define OFF_B_HI   151552     // half[32][296] = 18944 -> 170496
#define OFF_GATES  170496     // float[128][36] = 18432 -> 188928
#define OFF_HT     188928     // float[32][34]  = 4352 -> 193280
#define OFF_WOUT2  193280     // ull[32 o][17]  = 4352 -> 197632
#define OFF_BOUT   197632     // float[4]
#define SMEM_BYTES 197648

__global__ void __launch_bounds__(NTHR, 1)
lstm_kernel(const float* __restrict__ x, const float* __restrict__ phys,
            const float* __restrict__ Wih, const float* __restrict__ Whh,
            const float* __restrict__ bih, const float* __restrict__ bhh,
            const float* __restrict__ Wout, const float* __restrict__ bout,
            float* __restrict__ out) {
    extern __shared__ __align__(128) char smem[];
    uint32_t sbase;
    asm("{ .reg .u64 t; cvta.to.shared.u64 t, %1; cvt.u32.u64 %0, t; }" : "=r"(sbase) : "l"(smem));

    float* gates   = (float*)(smem + OFF_GATES);
    float* htile   = (float*)(smem + OFF_HT);
    ull*   wout2_s = (ull*)(smem + OFF_WOUT2);
    float* bout_s  = (float*)(smem + OFF_BOUT);

    const int tid  = threadIdx.x;
    const int cta  = blockIdx.x;
    const int grp  = cta >> 3;
    const int g8   = cta & 7;
    const int b0   = grp * BT;
    const int j0   = g8 * 32;
    const int w    = tid >> 5;
    const int lane = tid & 31;
    const int b    = tid >> 3;     // batch row 0..31 (writeback map)
    const int s    = tid & 7;      // k-slice 0..7

    // ---- zero B tile once (pad cols 288..295 stay 0 forever) ----
    for (int i = tid; i < 18944 / 16; i += NTHR)
        ((uint4*)(smem + OFF_B_HI))[i] = make_uint4(0, 0, 0, 0);

    // ---- A = weights fp16 hi/lo, row r = 4j+gate, 592B stride ----
    for (int i = tid; i < MROWS * KP; i += NTHR) {
        int r = i / KP, k = i - r * KP;
        int j = r >> 2, g = r & 3;
        int grow = g * HH + j0 + j;
        float v = 0.0f;
        if (k < HH)        v = Whh[grow * HH + k];
        else if (k < KDIM) v = Wih[grow * II + (k - HH)];
        __half h = __float2half_rn(v);
        __half l = __float2half_rn(v - __half2float(h));
        *(__half*)(smem + OFF_A_HI + r * RB + k * 2) = h;
        *(__half*)(smem + OFF_A_LO + r * RB + k * 2) = l;
    }
    // Wout pairs over OWN j-slice, all 32 o
    for (int i = tid; i < 32 * 16; i += NTHR) {
        int o = i >> 4, jp = i & 15;
        wout2_s[o * 17 + jp] = pack2(Wout[o * HH + j0 + 2 * jp],
                                     Wout[o * HH + j0 + 2 * jp + 1]);
    }
    if (tid < 4) bout_s[tid] = bout[g8 * 4 + tid];

    // MMA fragment lane mapping (validated R8-R14)
    const int m  = lane >> 3;
    const int r8 = lane & 7;
    const int gq = lane >> 2;
    const int tg = lane & 3;
    const uint32_t aHi = sbase + OFF_A_HI + (16 * w + ((m & 1) << 3) + r8) * RB + ((m >> 1) << 4);
    const uint32_t aLo = aHi + (OFF_A_LO - OFF_A_HI);
    const uint32_t bHi = sbase + OFF_B_HI + (((m >> 1) << 3) + r8) * RB + ((m & 1) << 4);

    // bias folded into D-register init (rows 16w+gq, 16w+gq+8)
    float bias_lo, bias_hi;
    {
        int r1 = 16 * w + gq, r2 = r1 + 8;
        int j1 = r1 >> 2, gg1 = r1 & 3, j2 = r2 >> 2, gg2 = r2 & 3;
        bias_lo = bih[gg1 * HH + j0 + j1] + bhh[gg1 * HH + j0 + j1];
        bias_hi = bih[gg2 * HH + j0 + j2] + bhh[gg2 * HH + j0 + j2];
    }

    // epilogue ownership: lane -> (jc = 4w + (lane>>3), batches 4*(lane&7)..+4)
    const int jloc = lane >> 3;          // 0..3
    const int bq4  = (lane & 7) * 4;
    float c[4] = {0.f, 0.f, 0.f, 0.f};
    __syncthreads();

    // ---- prologue: stage x(0) into B x-cols (h(0)=0 via zero fill) ----
    {
        float4 xv = *(const float4*)(x + (size_t)(b0 + b) * II + s * 4);
        uint32_t u0 = h2u(__floats2half2_rn(xv.x, xv.y));
        uint32_t u1 = h2u(__floats2half2_rn(xv.z, xv.w));
        *(uint2*)(smem + OFF_B_HI + b * RB + 512 + s * 8) = make_uint2(u0, u1);
    }
    __syncthreads();

    for (int t = 0; t < TT; ++t) {
        // ---- top prefetches (independent of peers) ----
        float4 xv = make_float4(0.f, 0.f, 0.f, 0.f);
        if (t + 1 < TT)
            xv = *(const float4*)(x + ((size_t)(t + 1) * BB + b0 + b) * II + s * 4);
        float phv = 0.0f;
        if (t > 0 && tid < 128)
            phv = phys[((size_t)(t - 1) * BB + b0 + (tid >> 2)) * OO + g8 * 4 + (tid & 3)];

        // ---- per-producer spin: warp w waits only for producer w, copies its slice ----
        if (t > 0) {
            if (lane == 0) {
                unsigned target = 8u * (unsigned)t;
                while (ld_acquire_u32(&g_bar[grp][w][0]) < target) { }
            }
            __syncwarp();
            const char* srcB = (const char*)&g_hf16[t & 1][grp][0][32 * w] + (lane & 3) * 16;
            char* dstB = smem + OFF_B_HI + w * 64 + (lane & 3) * 16;
#pragma unroll
            for (int pass = 0; pass < 4; ++pass) {
                int bb = 8 * pass + (lane >> 2);
                uint4 v = *(const uint4*)(srcB + (size_t)bb * (HH * 2));
                *(uint4*)(dstB + bb * RB) = v;
            }
        }
        __syncthreads();

        // ---- gate GEMM: 2-pass fp16-split (Whi + Wlo) x h_fp16 ----
        float d[4][4];
#pragma unroll
        for (int nt = 0; nt < 4; ++nt) {
            d[nt][0] = bias_lo; d[nt][1] = bias_lo;
            d[nt][2] = bias_hi; d[nt][3] = bias_hi;
        }
#pragma unroll 6
        for (int kc = 0; kc < NCHUNK; ++kc) {
            uint32_t a[4], a2[4], qh[8];
            ldsm4(a,      aHi + kc * 32);
            ldsm4(qh,     bHi + kc * 32);
            ldsm4(qh + 4, bHi + 16 * RB + kc * 32);
            ldsm4(a2,     aLo + kc * 32);
            mma16816(d[0], a,  qh[0], qh[1]);
            mma16816(d[1], a,  qh[2], qh[3]);
            mma16816(d[2], a,  qh[4], qh[5]);
            mma16816(d[3], a,  qh[6], qh[7]);
            mma16816(d[0], a2, qh[0], qh[1]);
            mma16816(d[1], a2, qh[2], qh[3]);
            mma16816(d[2], a2, qh[4], qh[5]);
            mma16816(d[3], a2, qh[6], qh[7]);
        }
        // D -> gates rows 16w..16w+16 (warp-local region, stride 36)
        {
            float* glo = gates + (16 * w + gq) * 36 + 2 * tg;
            float* ghi = glo + 8 * 36;
#pragma unroll
            for (int nt = 0; nt < 4; ++nt) {
                glo[8 * nt] = d[nt][0]; glo[8 * nt + 1] = d[nt][1];
                ghi[8 * nt] = d[nt][2]; ghi[8 * nt + 1] = d[nt][3];
            }
        }
        __syncwarp();   // warp-local STS->LDS visibility (rows owned by this warp only)

        // ---- LSTM epilogue (warp-local): lane = (jc, batches bq4..bq4+4) ----
        {
            const float* gr = gates + (16 * w + 4 * jloc) * 36 + bq4;
            float4 vi = *(const float4*)(gr);
            float4 vf = *(const float4*)(gr + 36);
            float4 vg = *(const float4*)(gr + 72);
            float4 vo = *(const float4*)(gr + 108);
            float gi_[4] = {vi.x, vi.y, vi.z, vi.w};
            float gf_[4] = {vf.x, vf.y, vf.z, vf.w};
            float gg_[4] = {vg.x, vg.y, vg.z, vg.w};
            float go_[4] = {vo.x, vo.y, vo.z, vo.w};
            int jc = 4 * w + jloc;
#pragma unroll
            for (int i = 0; i < 4; ++i) {
                float ig = sigf(gi_[i]), fg = sigf(gf_[i]);
                float gt = tanhfast(gg_[i]), og = sigf(go_[i]);
                float cn = fg * c[i] + ig * gt;
                c[i] = cn;
                htile[(bq4 + i) * 34 + jc] = og * tanhfast(cn);
            }
        }

        // ---- output for step t-1 (overlaps the htile sync) ----
        if (t > 0 && tid < 128) {
            int bq = tid >> 2, o = tid & 3, oc = g8 * 4 + o;
            float rnn = bout_s[o];
            const float* pp = &g_part[t & 1][grp][0][bq][oc];
#pragma unroll
            for (int p = 0; p < 8; ++p) rnn += pp[(size_t)p * BT * OO];
            size_t oi = ((size_t)(b0 + bq) * TT + (t - 1)) * OO + oc;
            out[oi] = phv + rnn;
            out[(size_t)BB * TT * OO + oi] = rnn;
        }
        __syncthreads();

        // ---- writeback h fp16 + out-proj partial + stage x(t+1) ----
        {
            float f0 = htile[b * 34 + 4 * s + 0];
            float f1 = htile[b * 34 + 4 * s + 1];
            float f2 = htile[b * 34 + 4 * s + 2];
            float f3 = htile[b * 34 + 4 * s + 3];
            __half2 h01 = __floats2half2_rn(f0, f1);
            __half2 h23 = __floats2half2_rn(f2, f3);
            *(uint2*)(&g_hf16[(t + 1) & 1][grp][b][j0 + 4 * s]) = make_uint2(h2u(h01), h2u(h23));
        }
        {
            int o4 = s * 4;
            const ull* hrow2 = (const ull*)(htile + b * 34);
            ull pa0 = 0ull, pa1 = 0ull, pa2 = 0ull, pa3 = 0ull;
#pragma unroll
            for (int jp = 0; jp < 16; ++jp) {
                ull h2 = hrow2[jp];
                ffma2(pa0, h2, wout2_s[(o4 + 0) * 17 + jp]);
                ffma2(pa1, h2, wout2_s[(o4 + 1) * 17 + jp]);
                ffma2(pa2, h2, wout2_s[(o4 + 2) * 17 + jp]);
                ffma2(pa3, h2, wout2_s[(o4 + 3) * 17 + jp]);
            }
            float2 q0 = unpack2(pa0), q1 = unpack2(pa1);
            float2 q2 = unpack2(pa2), q3 = unpack2(pa3);
            *(float4*)(&g_part[(t + 1) & 1][grp][g8][b][o4]) =
                make_float4(q0.x + q0.y, q1.x + q1.y, q2.x + q2.y, q3.x + q3.y);
        }
        if (t + 1 < TT) {   // stage x(t+1) into B x-cols (B free after this sync point)
            uint32_t u0 = h2u(__floats2half2_rn(xv.x, xv.y));
            uint32_t u1 = h2u(__floats2half2_rn(xv.z, xv.w));
            *(uint2*)(smem + OFF_B_HI + b * RB + 512 + s * 8) = make_uint2(u0, u1);
        }
        // per-warp release of OWN producer flag (orders this warp's STGs)
        __syncwarp();
        if (lane == 0) red_release_add(&g_bar[grp][g8][0], 1u);
    }

    // ---- final output for step TT-1 ----
    if (lane == 0) {
        unsigned target = 8u * (unsigned)TT;
        while (ld_acquire_u32(&g_bar[grp][w][0]) < target) { }
    }
    __syncwarp();
    __syncthreads();
    if (tid < 128) {
        int bq = tid >> 2, o = tid & 3, oc = g8 * 4 + o;
        float phv = phys[((size_t)(TT - 1) * BB + b0 + bq) * OO + oc];
        float rnn = bout_s[o];
        const float* pp = &g_part[TT & 1][grp][0][bq][oc];
#pragma unroll
        for (int p = 0; p < 8; ++p) rnn += pp[(size_t)p * BT * OO];
        size_t oi = ((size_t)(b0 + bq) * TT + (TT - 1)) * OO + oc;
        out[oi] = phv + rnn;
        out[(size_t)BB * TT * OO + oi] = rnn;
    }
}

extern "C" void kernel_launch(void* const* d_in, const int* in_sizes, int n_in,
                              void* d_out, int out_size) {
    const float* x    = (const float*)d_in[0];
    const float* phys = (const float*)d_in[1];
    const float* Wih  = (const float*)d_in[2];
    const float* Whh  = (const float*)d_in[3];
    const float* bih  = (const float*)d_in[4];
    const float* bhh  = (const float*)d_in[5];
    const float* Wout = (const float*)d_in[6];
    const float* bout = (const float*)d_in[7];
    float* out = (float*)d_out;

    cudaFuncSetAttribute(lstm_kernel,
                         cudaFuncAttributeMaxDynamicSharedMemorySize,
                         SMEM_BYTES);

    init_kernel<<<(131072 + 255) / 256, 256>>>();
    lstm_kernel<<<NGRP * 8, NTHR, SMEM_BYTES>>>(x, phys, Wih, Whh, bih, bhh,
                                                Wout, bout, out);
}

// round 16
// speedup vs baseline: 2.2007x; 1.1439x over previous
#include <cuda_runtime.h>
#include <cuda_fp16.h>
#include <cstdint>
#include <cstddef>

// Problem constants
#define TT   1024
#define BB   512
#define II   32
#define HH   256
#define OO   32
#define KDIM 288
#define NCHUNK 18        // 288/16 k-chunks

#define NGRP 16          // batch groups (32 rows each)
#define BT   32
#define NTHR 256         // 8 warps, warp w owns D rows [16w,16w+16) = j [4w,4w+4)
#define MROWS 128        // gate rows per CTA, r = 4*j + gate
#define KP   296         // padded halfs per row
#define RB   592         // row bytes (rows mod 128 all distinct -> conflict-free ldsm)

typedef unsigned long long ull;

// Persistent scratch (no allocation allowed)
__device__ __align__(16) __half g_hf16[2][NGRP][BT][HH];    // h fp16 [par][grp][b][j]
__device__ __align__(16) float  g_part[2][NGRP][8][BT][OO]; // out-proj partials
__device__ unsigned             g_bar[NGRP][8][8];          // per-producer flags, 32B padded

__global__ void init_kernel() {
    int idx = blockIdx.x * blockDim.x + threadIdx.x;
    if (idx < 131072) ((unsigned*)g_hf16)[idx] = 0u;        // zero both parities
    if (idx < NGRP * 8 * 8) ((unsigned*)g_bar)[idx] = 0u;
}

// ---------- helpers ----------
__device__ __forceinline__ void ffma2(ull& acc, ull a, ull b) {
    asm("fma.rn.f32x2 %0, %1, %2, %0;" : "+l"(acc) : "l"(a), "l"(b));
}
__device__ __forceinline__ ull pack2(float a, float b) {
    ull r; asm("mov.b64 %0, {%1, %2};" : "=l"(r) : "f"(a), "f"(b)); return r;
}
__device__ __forceinline__ float2 unpack2(ull v) {
    float2 r; asm("mov.b64 {%0, %1}, %2;" : "=f"(r.x), "=f"(r.y) : "l"(v)); return r;
}
__device__ __forceinline__ unsigned ld_acquire_u32(const unsigned* p) {
    unsigned v;
    asm volatile("ld.acquire.gpu.u32 %0, [%1];" : "=r"(v) : "l"(p));
    return v;
}
__device__ __forceinline__ void red_release_add(unsigned* p, unsigned v) {
    asm volatile("red.release.gpu.global.add.u32 [%0], %1;" :: "l"(p), "r"(v) : "memory");
}
__device__ __forceinline__ float sigf(float x) {
    return __fdividef(1.0f, 1.0f + __expf(-x));
}
__device__ __forceinline__ float tanhfast(float x) {
    float y; asm("tanh.approx.f32 %0, %1;" : "=f"(y) : "f"(x)); return y;
}
__device__ __forceinline__ uint32_t h2u(__half2 h) { return *reinterpret_cast<uint32_t*>(&h); }

__device__ __forceinline__ void ldsm4(uint32_t* r, uint32_t addr) {
    asm volatile("ldmatrix.sync.aligned.m8n8.x4.shared.b16 {%0,%1,%2,%3}, [%4];"
                 : "=r"(r[0]), "=r"(r[1]), "=r"(r[2]), "=r"(r[3]) : "r"(addr));
}
__device__ __forceinline__ void mma16816(float* d, const uint32_t* a, uint32_t b0, uint32_t b1) {
    asm volatile("mma.sync.aligned.m16n8k16.row.col.f32.f16.f16.f32 "
                 "{%0,%1,%2,%3}, {%4,%5,%6,%7}, {%8,%9}, {%0,%1,%2,%3};"
                 : "+f"(d[0]), "+f"(d[1]), "+f"(d[2]), "+f"(d[3])
                 : "r"(a[0]), "r"(a[1]), "r"(a[2]), "r"(a[3]), "r"(b0), "r"(b1));
}

// smem byte offsets (A_LO deleted; A smem only used at init for the preload)
#define OFF_A_HI   0          // half[128][296] = 75776
#define OFF_B_HI   75776      // half[32][296] = 18944 -> 94720
#define OFF_GATES  94720      // float[128][36] = 18432 -> 113152
#define OFF_HT     113152     // float[32][34]  = 4352 -> 117504
#define OFF_WOUT2  117504     // ull[32 o][17]  = 4352 -> 121856
#define OFF_BOUT   121856     // float[4]
#define SMEM_BYTES 121872

__global__ void __launch_bounds__(NTHR, 1)
lstm_kernel(const float* __restrict__ x, const float* __restrict__ phys,
            const float* __restrict__ Wih, const float* __restrict__ Whh,
            const float* __restrict__ bih, const float* __restrict__ bhh,
            const float* __restrict__ Wout, const float* __restrict__ bout,
            float* __restrict__ out) {
    extern __shared__ __align__(128) char smem[];
    uint32_t sbase;
    asm("{ .reg .u64 t; cvta.to.shared.u64 t, %1; cvt.u32.u64 %0, t; }" : "=r"(sbase) : "l"(smem));

    float* gates   = (float*)(smem + OFF_GATES);
    float* htile   = (float*)(smem + OFF_HT);
    ull*   wout2_s = (ull*)(smem + OFF_WOUT2);
    float* bout_s  = (float*)(smem + OFF_BOUT);

    const int tid  = threadIdx.x;
    const int cta  = blockIdx.x;
    const int grp  = cta >> 3;
    const int g8   = cta & 7;
    const int b0   = grp * BT;
    const int j0   = g8 * 32;
    const int w    = tid >> 5;
    const int lane = tid & 31;
    const int b    = tid >> 3;     // batch row 0..31 (writeback map)
    const int s    = tid & 7;      // k-slice 0..7

    // ---- zero B tile once (pad cols 288..295 stay 0 forever) ----
    for (int i = tid; i < 18944 / 16; i += NTHR)
        ((uint4*)(smem + OFF_B_HI))[i] = make_uint4(0, 0, 0, 0);

    // ---- A = weights fp16 (1-pass: hi only), row r = 4j+gate, 592B stride ----
    for (int i = tid; i < MROWS * KP; i += NTHR) {
        int r = i / KP, k = i - r * KP;
        int j = r >> 2, g = r & 3;
        int grow = g * HH + j0 + j;
        float v = 0.0f;
        if (k < HH)        v = Whh[grow * HH + k];
        else if (k < KDIM) v = Wih[grow * II + (k - HH)];
        *(__half*)(smem + OFF_A_HI + r * RB + k * 2) = __float2half_rn(v);
    }
    // Wout pairs over OWN j-slice, all 32 o
    for (int i = tid; i < 32 * 16; i += NTHR) {
        int o = i >> 4, jp = i & 15;
        wout2_s[o * 17 + jp] = pack2(Wout[o * HH + j0 + 2 * jp],
                                     Wout[o * HH + j0 + 2 * jp + 1]);
    }
    if (tid < 4) bout_s[tid] = bout[g8 * 4 + tid];

    // MMA fragment lane mapping (validated R8-R15)
    const int m  = lane >> 3;
    const int r8 = lane & 7;
    const int gq = lane >> 2;
    const int tg = lane & 3;
    const uint32_t aHi = sbase + OFF_A_HI + (16 * w + ((m & 1) << 3) + r8) * RB + ((m >> 1) << 4);
    const uint32_t bHi = sbase + OFF_B_HI + (((m >> 1) << 3) + r8) * RB + ((m & 1) << 4);

    // bias folded into D-register init (rows 16w+gq, 16w+gq+8)
    float bias_lo, bias_hi;
    {
        int r1 = 16 * w + gq, r2 = r1 + 8;
        int j1 = r1 >> 2, gg1 = r1 & 3, j2 = r2 >> 2, gg2 = r2 & 3;
        bias_lo = bih[gg1 * HH + j0 + j1] + bhh[gg1 * HH + j0 + j1];
        bias_hi = bih[gg2 * HH + j0 + j2] + bhh[gg2 * HH + j0 + j2];
    }

    // epilogue ownership: lane -> (jc = 4w + (lane>>3), batches 4*(lane&7)..+4)
    const int jloc = lane >> 3;          // 0..3
    const int bq4  = (lane & 7) * 4;
    float c[4] = {0.f, 0.f, 0.f, 0.f};
    __syncthreads();

    // ---- A fragments resident in registers for the whole rollout ----
    uint32_t afrag[NCHUNK][4];
#pragma unroll
    for (int kc = 0; kc < NCHUNK; ++kc)
        ldsm4(afrag[kc], aHi + kc * 32);

    // ---- prologue: stage x(0) into B x-cols (h(0)=0 via zero fill) ----
    {
        float4 xv = *(const float4*)(x + (size_t)(b0 + b) * II + s * 4);
        uint32_t u0 = h2u(__floats2half2_rn(xv.x, xv.y));
        uint32_t u1 = h2u(__floats2half2_rn(xv.z, xv.w));
        *(uint2*)(smem + OFF_B_HI + b * RB + 512 + s * 8) = make_uint2(u0, u1);
    }
    __syncthreads();

    for (int t = 0; t < TT; ++t) {
        // ---- top prefetches (independent of peers) ----
        float4 xv = make_float4(0.f, 0.f, 0.f, 0.f);
        if (t + 1 < TT)
            xv = *(const float4*)(x + ((size_t)(t + 1) * BB + b0 + b) * II + s * 4);
        float phv = 0.0f;
        if (t > 0 && tid < 128)
            phv = phys[((size_t)(t - 1) * BB + b0 + (tid >> 2)) * OO + g8 * 4 + (tid & 3)];

        // ---- per-producer spin: warp w waits only for producer w, copies its slice ----
        if (t > 0) {
            if (lane == 0) {
                unsigned target = 8u * (unsigned)t;
                while (ld_acquire_u32(&g_bar[grp][w][0]) < target) { }
            }
            __syncwarp();
            const char* srcB = (const char*)&g_hf16[t & 1][grp][0][32 * w] + (lane & 3) * 16;
            char* dstB = smem + OFF_B_HI + w * 64 + (lane & 3) * 16;
#pragma unroll
            for (int pass = 0; pass < 4; ++pass) {
                int bb = 8 * pass + (lane >> 2);
                uint4 v = *(const uint4*)(srcB + (size_t)bb * (HH * 2));
                *(uint4*)(dstB + bb * RB) = v;
            }
        }
        __syncthreads();

        // ---- gate GEMM: 1-pass fp16, A resident in registers ----
        float d[4][4];
#pragma unroll
        for (int nt = 0; nt < 4; ++nt) {
            d[nt][0] = bias_lo; d[nt][1] = bias_lo;
            d[nt][2] = bias_hi; d[nt][3] = bias_hi;
        }
#pragma unroll
        for (int kc = 0; kc < NCHUNK; ++kc) {
            uint32_t qh[8];
            ldsm4(qh,     bHi + kc * 32);
            ldsm4(qh + 4, bHi + 16 * RB + kc * 32);
            mma16816(d[0], afrag[kc], qh[0], qh[1]);
            mma16816(d[1], afrag[kc], qh[2], qh[3]);
            mma16816(d[2], afrag[kc], qh[4], qh[5]);
            mma16816(d[3], afrag[kc], qh[6], qh[7]);
        }
        // D -> gates rows 16w..16w+16 (warp-local region, stride 36)
        {
            float* glo = gates + (16 * w + gq) * 36 + 2 * tg;
            float* ghi = glo + 8 * 36;
#pragma unroll
            for (int nt = 0; nt < 4; ++nt) {
                glo[8 * nt] = d[nt][0]; glo[8 * nt + 1] = d[nt][1];
                ghi[8 * nt] = d[nt][2]; ghi[8 * nt + 1] = d[nt][3];
            }
        }
        __syncwarp();   // warp-local STS->LDS visibility (rows owned by this warp only)

        // ---- LSTM epilogue (warp-local): lane = (jc, batches bq4..bq4+4) ----
        {
            const float* gr = gates + (16 * w + 4 * jloc) * 36 + bq4;
            float4 vi = *(const float4*)(gr);
            float4 vf = *(const float4*)(gr + 36);
            float4 vg = *(const float4*)(gr + 72);
            float4 vo = *(const float4*)(gr + 108);
            float gi_[4] = {vi.x, vi.y, vi.z, vi.w};
            float gf_[4] = {vf.x, vf.y, vf.z, vf.w};
            float gg_[4] = {vg.x, vg.y, vg.z, vg.w};
            float go_[4] = {vo.x, vo.y, vo.z, vo.w};
            int jc = 4 * w + jloc;
#pragma unroll
            for (int i = 0; i < 4; ++i) {
                float ig = sigf(gi_[i]), fg = sigf(gf_[i]);
                float gt = tanhfast(gg_[i]), og = sigf(go_[i]);
                float cn = fg * c[i] + ig * gt;
                c[i] = cn;
                htile[(bq4 + i) * 34 + jc] = og * tanhfast(cn);
            }
        }

        // ---- output for step t-1 (overlaps the htile sync) ----
        if (t > 0 && tid < 128) {
            int bq = tid >> 2, o = tid & 3, oc = g8 * 4 + o;
            float rnn = bout_s[o];
            const float* pp = &g_part[t & 1][grp][0][bq][oc];
#pragma unroll
            for (int p = 0; p < 8; ++p) rnn += pp[(size_t)p * BT * OO];
            size_t oi = ((size_t)(b0 + bq) * TT + (t - 1)) * OO + oc;
            out[oi] = phv + rnn;
            out[(size_t)BB * TT * OO + oi] = rnn;
        }
        __syncthreads();

        // ---- writeback h fp16 + out-proj partial + stage x(t+1) ----
        {
            float f0 = htile[b * 34 + 4 * s + 0];
            float f1 = htile[b * 34 + 4 * s + 1];
            float f2 = htile[b * 34 + 4 * s + 2];
            float f3 = htile[b * 34 + 4 * s + 3];
            __half2 h01 = __floats2half2_rn(f0, f1);
            __half2 h23 = __floats2half2_rn(f2, f3);
            *(uint2*)(&g_hf16[(t + 1) & 1][grp][b][j0 + 4 * s]) = make_uint2(h2u(h01), h2u(h23));
        }
        {
            int o4 = s * 4;
            const ull* hrow2 = (const ull*)(htile + b * 34);
            ull pa0 = 0ull, pa1 = 0ull, pa2 = 0ull, pa3 = 0ull;
#pragma unroll
            for (int jp = 0; jp < 16; ++jp) {
                ull h2 = hrow2[jp];
                ffma2(pa0, h2, wout2_s[(o4 + 0) * 17 + jp]);
                ffma2(pa1, h2, wout2_s[(o4 + 1) * 17 + jp]);
                ffma2(pa2, h2, wout2_s[(o4 + 2) * 17 + jp]);
                ffma2(pa3, h2, wout2_s[(o4 + 3) * 17 + jp]);
            }
            float2 q0 = unpack2(pa0), q1 = unpack2(pa1);
            float2 q2 = unpack2(pa2), q3 = unpack2(pa3);
            *(float4*)(&g_part[(t + 1) & 1][grp][g8][b][o4]) =
                make_float4(q0.x + q0.y, q1.x + q1.y, q2.x + q2.y, q3.x + q3.y);
        }
        if (t + 1 < TT) {   // stage x(t+1) into B x-cols (B free after this sync point)
            uint32_t u0 = h2u(__floats2half2_rn(xv.x, xv.y));
            uint32_t u1 = h2u(__floats2half2_rn(xv.z, xv.w));
            *(uint2*)(smem + OFF_B_HI + b * RB + 512 + s * 8) = make_uint2(u0, u1);
        }
        // per-warp release of OWN producer flag (orders this warp's STGs)
        __syncwarp();
        if (lane == 0) red_release_add(&g_bar[grp][g8][0], 1u);
    }

    // ---- final output for step TT-1 ----
    if (lane == 0) {
        unsigned target = 8u * (unsigned)TT;
        while (ld_acquire_u32(&g_bar[grp][w][0]) < target) { }
    }
    __syncwarp();
    __syncthreads();
    if (tid < 128) {
        int bq = tid >> 2, o = tid & 3, oc = g8 * 4 + o;
        float phv = phys[((size_t)(TT - 1) * BB + b0 + bq) * OO + oc];
        float rnn = bout_s[o];
        const float* pp = &g_part[TT & 1][grp][0][bq][oc];
#pragma unroll
        for (int p = 0; p < 8; ++p) rnn += pp[(size_t)p * BT * OO];
        size_t oi = ((size_t)(b0 + bq) * TT + (TT - 1)) * OO + oc;
        out[oi] = phv + rnn;
        out[(size_t)BB * TT * OO + oi] = rnn;
    }
}

extern "C" void kernel_launch(void* const* d_in, const int* in_sizes, int n_in,
                              void* d_out, int out_size) {
    const float* x    = (const float*)d_in[0];
    const float* phys = (const float*)d_in[1];
    const float* Wih  = (const float*)d_in[2];
    const float* Whh  = (const float*)d_in[3];
    const float* bih  = (const float*)d_in[4];
    const float* bhh  = (const float*)d_in[5];
    const float* Wout = (const float*)d_in[6];
    const float* bout = (const float*)d_in[7];
    float* out = (float*)d_out;

    cudaFuncSetAttribute(lstm_kernel,
                         cudaFuncAttributeMaxDynamicSharedMemorySize,
                         SMEM_BYTES);

    init_kernel<<<(131072 + 255) / 256, 256>>>();
    lstm_kernel<<<NGRP * 8, NTHR, SMEM_BYTES>>>(x, phys, Wih, Whh, bih, bhh,
                                                Wout, bout, out);
}